// round 16
// baseline (speedup 1.0000x reference)
#include <cuda_runtime.h>
#include <cstdint>
#include <math.h>

// NetSimile on 8 block-diagonal graphs of 512 nodes, dense A[4096,4096] in {0,1}.
// THREE launches: bits -> feat -> rest(f3 + stats fused).
// Stats warps for f!=3 depend only on feat (prior launch) and run immediately,
// overlapping f3. Only the 8 (g,f=3) warps spin on per-graph counters.

#define NN 4096
#define GG 8
#define MM 512
#define WW 16    // 512 bits = 16 u32 words per row
#define LMAX 64  // ego1 list capacity (deg+1, max deg ~35 whp)

#define B_F3 512
#define B_ST 7
#define NBLK_REST (B_F3 + B_ST)

__device__ uint32_t g_bits[NN][WW];   // adjacency bitsets (no self bit)
__device__ int      g_deg[NN];
__device__ float    g_feat[7][NN];
__device__ int      ctr_f3[GG];       // zero-init; self-reset each run

__device__ __forceinline__ void spin_ge(volatile int* c, int target) {
    while (*c < target) __nanosleep(64);
}

// ---------------------------------------------------------------------------
// K1: build per-row bitsets + degree. One warp per row, MLP-16 loads.
// ---------------------------------------------------------------------------
__global__ void k_bits(const float* __restrict__ A) {
    int warp = (blockIdx.x * blockDim.x + threadIdx.x) >> 5;
    int lane = threadIdx.x & 31;
    if (warp >= NN) return;
    int g = warp / MM;
    const float* row = A + (size_t)warp * NN + (size_t)g * MM;

    float v[WW];
#pragma unroll
    for (int w = 0; w < WW; w++) v[w] = row[w * 32 + lane];

    uint32_t myword = 0;
    int deg = 0;
#pragma unroll
    for (int w = 0; w < WW; w++) {
        unsigned m = __ballot_sync(0xffffffffu, v[w] != 0.0f);
        deg += __popc(m);
        if (lane == w) myword = m;
    }
    if (lane < WW) g_bits[warp][lane] = myword;
    if (lane == 0) g_deg[warp] = deg;
}

// ---------------------------------------------------------------------------
// K2: sparse ego1-row feature pass (R14, measured fast).
// ---------------------------------------------------------------------------
__global__ void __launch_bounds__(256) k_feat() {
    __shared__ uint32_t sbits[MM][WW + 1];
    __shared__ int sdeg[MM];
    __shared__ uint16_t slist[8][LMAX];
    int tid = threadIdx.x;
    int wid = tid >> 5, lane = tid & 31;
    const unsigned FULL = 0xffffffffu;
    int node0 = blockIdx.x * 8;
    int g = node0 >> 9, base = g << 9;

    for (int idx = tid; idx < MM * WW; idx += 256) {
        int v = idx >> 4, w = idx & 15;
        sbits[v][w] = g_bits[base + v][w];
    }
    for (int idx = tid; idx < MM; idx += 256) sdeg[idx] = g_deg[base + idx];
    __syncthreads();

    int n = node0 + wid;
    int r = n - base;

    uint32_t w0 = (lane < WW) ? sbits[r][lane] : 0u;
    if (lane == (r >> 5)) w0 |= 1u << (r & 31);
    uint32_t m1w[WW];
#pragma unroll
    for (int w = 0; w < WW; w++) m1w[w] = __shfl_sync(FULL, w0, w);

    int pc = (lane < WW) ? __popc(w0) : 0;
    int off = pc;
#pragma unroll
    for (int o = 1; o < 32; o <<= 1) {
        int v = __shfl_up_sync(FULL, off, o);
        if (lane >= o) off += v;
    }
    int total = __shfl_sync(FULL, off, 31);   // = deg + 1
    if (total > LMAX) total = LMAX;
    off -= pc;
    uint32_t wrem = w0;
    while (wrem) {
        int b = __ffs(wrem) - 1;
        wrem &= wrem - 1;
        if (off < LMAX) slist[wid][off] = (uint16_t)(lane * 32 + b);
        off++;
    }
    __syncwarp();

    int f4 = 0, sumdegn = 0;
    uint32_t or16[WW];
#pragma unroll
    for (int w = 0; w < WW; w++) or16[w] = 0u;

    for (int i = lane; i < total; i += 32) {
        int v = slist[wid][i];
        int p = 0;
#pragma unroll
        for (int w = 0; w < WW; w++) {
            uint32_t aw = sbits[v][w];
            p += __popc(m1w[w] & aw);
            or16[w] |= aw;
        }
        f4 += p;
        if (v != r) sumdegn += sdeg[v];
    }
    f4      = __reduce_add_sync(FULL, f4);
    sumdegn = __reduce_add_sync(FULL, sumdegn);

    int cnt2 = 0;
#pragma unroll
    for (int w = 0; w < WW; w++) {
        or16[w] = __reduce_or_sync(FULL, or16[w]) | m1w[w];
        cnt2 += __popc(or16[w]);
    }

    int sumdeg2 = 0;
#pragma unroll
    for (int i = 0; i < WW; i++) {
        if ((or16[i] >> lane) & 1u) sumdeg2 += sdeg[i * 32 + lane];
    }
    sumdeg2 = __reduce_add_sync(FULL, sumdeg2);

    if (lane == 0) {
        float deg = (float)sdeg[r];
        g_feat[0][n] = deg;
        g_feat[1][n] = (deg > 1.f) ? 2.0f * ((float)f4 - deg) / (deg * (deg - 1.0f)) : 0.f;
        g_feat[2][n] = (deg > 0.f) ? (float)sumdegn / deg : 0.f;
        g_feat[4][n] = 0.5f * (float)f4;
        g_feat[5][n] = (float)sumdeg2 - 2.0f * (float)f4;
        g_feat[6][n] = (float)cnt2 - deg - 1.0f;
    }
}

// ---------------------------------------------------------------------------
// K3: f3 (512 blocks) + stats (7 blocks, warp per (g,f)) fused.
// f!=3 stats warps read feat output (prior launch) -> no spin, overlap f3.
// f==3 stats warps spin on ctr_f3[g]==64, then acquire-fence and read.
// ---------------------------------------------------------------------------
__global__ void __launch_bounds__(256) k_rest(float* __restrict__ out) {
    int bid = blockIdx.x;
    int tid = threadIdx.x, wid = tid >> 5, lane = tid & 31;
    const unsigned FULL = 0xffffffffu;

    // ============================== f3 phase ===============================
    if (bid < B_F3) {
        int n = bid * 8 + wid;               // warp per node
        int g = n >> 9, base = g << 9;
        float s = 0.f;
#pragma unroll
        for (int k = 0; k < WW; k++) {
            uint32_t w = g_bits[n][k];
            if ((w >> lane) & 1u) s += g_feat[1][base + k * 32 + lane];
        }
#pragma unroll
        for (int o = 16; o; o >>= 1) s += __shfl_xor_sync(FULL, s, o);
        if (lane == 0) {
            float deg = (float)g_deg[n];
            g_feat[3][n] = (deg > 0.f) ? s / deg : 0.f;
        }
        __threadfence();                      // release
        __syncthreads();
        if (tid == 0) atomicAdd(&ctr_f3[g], 1);
        return;
    }

    // ============================= stats phase =============================
    int id = (bid - B_F3) * 8 + wid;          // 0..55
    int g = id / 7, f = id % 7;
    int base = g * MM;

    if (f == 3) {                             // only these warps wait on f3
        if (lane == 0) spin_ge(&ctr_f3[g], 64);
        __syncwarp();
        __threadfence();                      // acquire
    }

    float xi[16];
#pragma unroll
    for (int j = 0; j < 16; j++) xi[j] = g_feat[f][base + lane + 32 * j];

    // ---- mean (fp32, pairwise) ----
    float pair8[8];
#pragma unroll
    for (int j = 0; j < 8; j++) pair8[j] = xi[2 * j] + xi[2 * j + 1];
    float q4a = (pair8[0] + pair8[1]) + (pair8[2] + pair8[3]);
    float q4b = (pair8[4] + pair8[5]) + (pair8[6] + pair8[7]);
    float sm = q4a + q4b;
#pragma unroll
    for (int o = 16; o; o >>= 1) sm += __shfl_xor_sync(FULL, sm, o);
    float mean = sm * (1.0f / (float)MM);

    // ---- median: 2-bit radix select with min/max early exit ----
    uint32_t keys[16];
#pragma unroll
    for (int j = 0; j < 16; j++) {
        uint32_t b = __float_as_uint(xi[j]);
        keys[j] = (b & 0x80000000u) ? ~b : (b ^ 0x80000000u);
    }
    uint32_t candm = 0xFFFFu;
    int k = (MM - 1) / 2;   // 255: value at sorted index 255
    uint32_t kv = 0;
    for (int bit = 30; bit >= 0; bit -= 2) {
        uint32_t mn = 0xFFFFFFFFu, mx = 0u, cnt = 0, bb = 0;
#pragma unroll
        for (int j = 0; j < 16; j++) {
            uint32_t kj = keys[j];
            uint32_t b = (kj >> bit) & 3u;
            bb |= b << (2 * j);
            if ((candm >> j) & 1u) {
                mn = min(mn, kj);
                mx = max(mx, kj);
                cnt += (b < 3u) ? (1u << (10 * b)) : 0u;  // c0|c1<<10|c2<<20
            }
        }
        mn = __reduce_min_sync(FULL, mn);
        mx = __reduce_max_sync(FULL, mx);
        if (mn == mx) { kv = mn; break; }
        cnt = __reduce_add_sync(FULL, cnt);
        int c0 = cnt & 1023, c1 = (cnt >> 10) & 1023, c2 = (cnt >> 20) & 1023;
        uint32_t chosen;
        if (k < c0)                { chosen = 0u; }
        else if (k < c0 + c1)      { chosen = 1u; k -= c0; }
        else if (k < c0 + c1 + c2) { chosen = 2u; k -= c0 + c1; }
        else                       { chosen = 3u; k -= c0 + c1 + c2; }
        kv |= chosen << bit;
#pragma unroll
        for (int j = 0; j < 16; j++)
            if (((bb >> (2 * j)) & 3u) != chosen) candm &= ~(1u << j);
    }
    uint32_t mb = (kv & 0x80000000u) ? (kv ^ 0x80000000u) : ~kv;
    float medv = __uint_as_float(mb);

    // ---- central moments 2,3,4 (fp32, pairwise) ----
    float a2[8], a3[8], a4[8];
#pragma unroll
    for (int j = 0; j < 8; j++) {
        float c0 = xi[2 * j] - mean,  c1 = xi[2 * j + 1] - mean;
        float p0 = c0 * c0,           p1 = c1 * c1;
        a2[j] = p0 + p1;
        a3[j] = fmaf(p0, c0, p1 * c1);
        a4[j] = fmaf(p0, p0, p1 * p1);
    }
    float s2 = ((a2[0]+a2[1])+(a2[2]+a2[3])) + ((a2[4]+a2[5])+(a2[6]+a2[7]));
    float s3 = ((a3[0]+a3[1])+(a3[2]+a3[3])) + ((a3[4]+a3[5])+(a3[6]+a3[7]));
    float s4 = ((a4[0]+a4[1])+(a4[2]+a4[3])) + ((a4[4]+a4[5])+(a4[6]+a4[7]));
#pragma unroll
    for (int o = 16; o; o >>= 1) {
        s2 += __shfl_xor_sync(FULL, s2, o);
        s3 += __shfl_xor_sync(FULL, s3, o);
        s4 += __shfl_xor_sync(FULL, s4, o);
    }

    if (lane == 0) {
        float m2 = s2 * (1.0f / (float)MM);
        float m3 = s3 * (1.0f / (float)MM);
        float m4 = s4 * (1.0f / (float)MM);
        float eps = 1e-4f;
        float sq = sqrtf(m2);
        out[g * 35 + 0  + f] = mean;
        out[g * 35 + 7  + f] = medv;
        out[g * 35 + 14 + f] = sq;
        out[g * 35 + 21 + f] = m3 / fmaxf(m2 * sq, eps);
        out[g * 35 + 28 + f] = m4 / fmaxf(m2 * m2, eps);
        if (f == 3) ctr_f3[g] = 0;   // self-reset for next replay (sole reader;
                                     // next increments only after kernel retires)
    }
}

extern "C" void kernel_launch(void* const* d_in, const int* in_sizes, int n_in,
                              void* d_out, int out_size) {
    const float* A = (const float*)d_in[0];
    float* out = (float*)d_out;

    k_bits<<<NN / 8, 256>>>(A);        // bitsets + degree (MLP-16 loads)
    k_feat<<<NN / 8, 256>>>();         // sparse ego1-row feature pass
    k_rest<<<NBLK_REST, 256>>>(out);   // f3 + stats fused (f!=3 overlaps f3)
}